// round 4
// baseline (speedup 1.0000x reference)
#include <cuda_runtime.h>
#include <math.h>

#define NMAX 100000
#define EMAX 1700000
#define DMAX 64
#define SCAN_CHUNK 512

typedef unsigned long long u64;

// ---------------- scratch (device globals; no allocation allowed) ----------
__device__ int   g_is64;
__device__ int   g_cnt[NMAX];
__device__ int   g_off[NMAX + 1];
__device__ int   g_part[1024];
__device__ int   g_esrc[EMAX];
__device__ float g_e[EMAX];
__device__ __align__(16) float g_h[(size_t)NMAX * DMAX];
__device__ __align__(16) float g_bufA[(size_t)NMAX * DMAX];
__device__ __align__(16) float g_bufB[(size_t)NMAX * DMAX];
__device__ float g_as[NMAX];
__device__ float g_ad[NMAX];

// ---------------- f32x2 helpers ----------------
__device__ __forceinline__ void fma2(u64& acc, u64 a, u64 b) {
    asm("fma.rn.f32x2 %0, %1, %2, %0;" : "+l"(acc) : "l"(a), "l"(b));
}
__device__ __forceinline__ float2 unpack2(u64 v) {
    unsigned int lo, hi;
    asm("mov.b64 {%0, %1}, %2;" : "=r"(lo), "=r"(hi) : "l"(v));
    return make_float2(__uint_as_float(lo), __uint_as_float(hi));
}

// ---------------- dtype detection ----------------
__global__ void detect_kernel(const unsigned int* __restrict__ w) {
    if (threadIdx.x != 0 || blockIdx.x != 0) return;
    int ok64 = 1;
#pragma unroll
    for (int i = 1; i < 128; i += 2) ok64 &= (w[i] == 0u);
    g_is64 = ok64;
}

__device__ __forceinline__ int load_idx(const void* eiv, long long pos) {
    if (g_is64) return (int)((const long long*)eiv)[pos];
    return ((const int*)eiv)[pos];
}

__device__ __forceinline__ int clampN(int v, int N) {
    return (v < 0) ? 0 : (v >= N ? N - 1 : v);
}

// ---------------- CSR build ----------------
__global__ void zero_cnt_kernel(int N) {
    int i = blockIdx.x * blockDim.x + threadIdx.x;
    if (i < N) g_cnt[i] = 0;
}

__global__ void hist_kernel(const void* __restrict__ eiv, int E, int Etot, int N) {
    int i = blockIdx.x * blockDim.x + threadIdx.x;
    if (i >= Etot) return;
    int d = (i < E) ? clampN(load_idx(eiv, (long long)E + i), N) : (i - E);
    atomicAdd(&g_cnt[d], 1);
}

__global__ void scan_reduce_kernel(int N) {
    __shared__ int sh[256];
    int b = blockIdx.x, t = threadIdx.x;
    int i0 = b * SCAN_CHUNK + t * 2;
    int s = 0;
    if (i0     < N) s += g_cnt[i0];
    if (i0 + 1 < N) s += g_cnt[i0 + 1];
    sh[t] = s;
    __syncthreads();
#pragma unroll
    for (int o = 128; o; o >>= 1) {
        if (t < o) sh[t] += sh[t + o];
        __syncthreads();
    }
    if (t == 0) g_part[b] = sh[0];
}

__global__ void scan_partials_kernel(int B, int N) {
    __shared__ int sh[1024];
    int t = threadIdx.x;
    int v = (t < B) ? g_part[t] : 0;
    sh[t] = v;
    __syncthreads();
#pragma unroll
    for (int o = 1; o < 1024; o <<= 1) {
        int u = (t >= o) ? sh[t - o] : 0;
        __syncthreads();
        sh[t] += u;
        __syncthreads();
    }
    if (t < B) g_part[t] = sh[t] - v;
    if (t == 1023) g_off[N] = sh[1023];
}

__global__ void scan_final_kernel(int N) {
    __shared__ int sh[256];
    int b = blockIdx.x, t = threadIdx.x;
    int i0 = b * SCAN_CHUNK + t * 2;
    int c0 = (i0     < N) ? g_cnt[i0]     : 0;
    int c1 = (i0 + 1 < N) ? g_cnt[i0 + 1] : 0;
    int s = c0 + c1;
    sh[t] = s;
    __syncthreads();
#pragma unroll
    for (int o = 1; o < 256; o <<= 1) {
        int u = (t >= o) ? sh[t - o] : 0;
        __syncthreads();
        sh[t] += u;
        __syncthreads();
    }
    int base = g_part[b] + sh[t] - s;
    if (i0 < N)     { g_off[i0]     = base;      g_cnt[i0]     = base; }
    if (i0 + 1 < N) { g_off[i0 + 1] = base + c0; g_cnt[i0 + 1] = base + c0; }
}

__global__ void scatter_kernel(const void* __restrict__ eiv, int E, int Etot, int N) {
    int i = blockIdx.x * blockDim.x + threadIdx.x;
    if (i >= Etot) return;
    int s, d;
    if (i < E) {
        s = clampN(load_idx(eiv, i), N);
        d = clampN(load_idx(eiv, (long long)E + i), N);
    } else {
        s = d = i - E;
    }
    int p = atomicAdd(&g_cnt[d], 1);
    if (p >= 0 && p < EMAX) g_esrc[p] = s;
}

// ---------------- GEMM (FFMA2) + fused attention dots ----------------
// h = X @ W  (X: [N,F], W: [F,D], D<=64, F%16==0); also g_as/g_ad = h @ a_s/a_d
// A stored DUPLICATED in smem so LDS.64 yields a packed (a,a) broadcast pair.
__global__ __launch_bounds__(256) void gemm_kernel(
    const float* __restrict__ Xext, int sel_in,
    const float* __restrict__ W,
    const float* __restrict__ a_s, const float* __restrict__ a_d,
    int N, int F, int D, int relu_in)
{
    const float* X = (sel_in == 0) ? Xext
                   : (sel_in == 1 ? (const float*)g_bufA : (const float*)g_bufB);
    __shared__ __align__(16) float xsd[16][132];   // duplicated: [k][2*node(+0/1)]
    __shared__ __align__(16) float ws[16][64];     // [k][col]
    __shared__ float as_s[64], ad_s[64];
    int tid  = threadIdx.x;
    int row0 = blockIdx.x * 64;
    int tr = tid >> 4, tc = tid & 15;
    u64 acc01[4] = {}, acc23[4] = {};              // rows i: cols(tc*4+0,1) / (tc*4+2,3)
    int lnode = tid >> 2, lq = tid & 3;
    int wcol = tid & 63, wk0 = (tid >> 6) << 2;

    if (tid < 64) {
        as_s[tid] = (tid < D) ? a_s[tid] : 0.f;
        ad_s[tid] = (tid < D) ? a_d[tid] : 0.f;
    }

    for (int k0 = 0; k0 < F; k0 += 16) {
        float4 xv = make_float4(0.f, 0.f, 0.f, 0.f);
        int gn = row0 + lnode;
        if (gn < N)
            xv = reinterpret_cast<const float4*>(X + (size_t)gn * F + k0)[lq];
        if (relu_in) {
            xv.x = fmaxf(xv.x, 0.f); xv.y = fmaxf(xv.y, 0.f);
            xv.z = fmaxf(xv.z, 0.f); xv.w = fmaxf(xv.w, 0.f);
        }
        // duplicated stores: (v, v) per element
        *(float2*)&xsd[lq * 4 + 0][2 * lnode] = make_float2(xv.x, xv.x);
        *(float2*)&xsd[lq * 4 + 1][2 * lnode] = make_float2(xv.y, xv.y);
        *(float2*)&xsd[lq * 4 + 2][2 * lnode] = make_float2(xv.z, xv.z);
        *(float2*)&xsd[lq * 4 + 3][2 * lnode] = make_float2(xv.w, xv.w);
#pragma unroll
        for (int j = 0; j < 4; j++) {
            int k = wk0 + j;
            ws[k][wcol] = (wcol < D) ? W[(size_t)(k0 + k) * D + wcol] : 0.f;
        }
        __syncthreads();
#pragma unroll
        for (int k = 0; k < 16; k++) {
            u64 b01 = *(const u64*)&ws[k][tc * 4];
            u64 b23 = *(const u64*)&ws[k][tc * 4 + 2];
            u64 a0 = *(const u64*)&xsd[k][2 * (tr * 4 + 0)];
            u64 a1 = *(const u64*)&xsd[k][2 * (tr * 4 + 1)];
            u64 a2 = *(const u64*)&xsd[k][2 * (tr * 4 + 2)];
            u64 a3 = *(const u64*)&xsd[k][2 * (tr * 4 + 3)];
            fma2(acc01[0], a0, b01); fma2(acc23[0], a0, b23);
            fma2(acc01[1], a1, b01); fma2(acc23[1], a1, b23);
            fma2(acc01[2], a2, b01); fma2(acc23[2], a2, b23);
            fma2(acc01[3], a3, b01); fma2(acc23[3], a3, b23);
        }
        __syncthreads();
    }

    // epilogue: store h + fused attention dot-products
    float sdot[4] = {}, ddot[4] = {};
    int c0 = tc * 4;
#pragma unroll
    for (int i = 0; i < 4; i++) {
        int n = row0 + tr * 4 + i;
        bool ok = (n < N);
        float2 v01 = unpack2(acc01[i]);
        float2 v23 = unpack2(acc23[i]);
        if (ok && c0 + 1 < D) *(float2*)&g_h[(size_t)n * D + c0]     = v01;
        if (ok && c0 + 3 < D) *(float2*)&g_h[(size_t)n * D + c0 + 2] = v23;
        float w0 = (c0     < D) ? v01.x : 0.f;
        float w1 = (c0 + 1 < D) ? v01.y : 0.f;
        float w2 = (c0 + 2 < D) ? v23.x : 0.f;
        float w3 = (c0 + 3 < D) ? v23.y : 0.f;
        sdot[i] += w0 * as_s[c0] + w1 * as_s[c0 + 1] + w2 * as_s[c0 + 2] + w3 * as_s[c0 + 3];
        ddot[i] += w0 * ad_s[c0] + w1 * ad_s[c0 + 1] + w2 * ad_s[c0 + 2] + w3 * ad_s[c0 + 3];
    }
#pragma unroll
    for (int o = 8; o; o >>= 1) {
#pragma unroll
        for (int i = 0; i < 4; i++) {
            sdot[i] += __shfl_xor_sync(0xffffffffu, sdot[i], o);
            ddot[i] += __shfl_xor_sync(0xffffffffu, ddot[i], o);
        }
    }
    if (tc == 0) {
#pragma unroll
        for (int i = 0; i < 4; i++) {
            int n = row0 + tr * 4 + i;
            if (n < N) { g_as[n] = sdot[i]; g_ad[n] = ddot[i]; }
        }
    }
}

// ---------------- fused segment softmax + aggregation (warp per dst) -------
__global__ void agg_kernel(float* OUText, int sel_out, int N, int D)
{
    float* OUT = (sel_out == 0) ? OUText : (sel_out == 1 ? g_bufA : g_bufB);
    int warp = (blockIdx.x * blockDim.x + threadIdx.x) >> 5;
    int lane = threadIdx.x & 31;
    int nw = (gridDim.x * blockDim.x) >> 5;
    const float2* H2 = reinterpret_cast<const float2*>(g_h);
    int rowst = D >> 1;

    for (int n = warp; n < N; n += nw) {
        int beg = g_off[n], end = g_off[n + 1];
        float adn = g_ad[n];

        // single pass: online softmax (max + sum), cache logits
        float m = -1e30f, s = 0.f;
        for (int p = beg + lane; p < end; p += 32) {
            float v = g_as[g_esrc[p]] + adn;
            v = (v > 0.f) ? v : 0.2f * v;
            g_e[p] = v;
            float mn = fmaxf(m, v);
            s = s * __expf(m - mn) + __expf(v - mn);
            m = mn;
        }
#pragma unroll
        for (int o = 16; o; o >>= 1) {
            float mo = __shfl_xor_sync(0xffffffffu, m, o);
            float so = __shfl_xor_sync(0xffffffffu, s, o);
            float mn = fmaxf(m, mo);
            s = s * __expf(m - mn) + so * __expf(mo - mn);
            m = mn;
        }
        float inv = 1.f / (s + 1e-16f);

        // aggregation: out[n,:] = sum_e softmax_e * h[src_e,:]  (lane owns 2 cols)
        int c0 = lane * 2;
        bool act = (c0 < D);
        float2 acc = make_float2(0.f, 0.f);
        int p = beg;
        for (; p + 1 < end; p += 2) {
            float a0 = __expf(g_e[p]     - m) * inv;
            float a1 = __expf(g_e[p + 1] - m) * inv;
            int s0 = g_esrc[p];
            int s1 = g_esrc[p + 1];
            if (act) {
                float2 h0 = H2[(size_t)s0 * rowst + lane];
                float2 h1 = H2[(size_t)s1 * rowst + lane];
                acc.x += a0 * h0.x + a1 * h1.x;
                acc.y += a0 * h0.y + a1 * h1.y;
            }
        }
        if (p < end) {
            float a0 = __expf(g_e[p] - m) * inv;
            int s0 = g_esrc[p];
            if (act) {
                float2 h0 = H2[(size_t)s0 * rowst + lane];
                acc.x += a0 * h0.x;
                acc.y += a0 * h0.y;
            }
        }
        if (act) {
            OUT[(size_t)n * D + c0]     = acc.x;
            OUT[(size_t)n * D + c0 + 1] = acc.y;
        }
    }
}

// ---------------- launch ----------------
extern "C" void kernel_launch(void* const* d_in, const int* in_sizes, int n_in,
                              void* d_out, int out_size)
{
    const float* x     = (const float*)d_in[0];
    const void*  ei    = d_in[1];
    const float* W0    = (const float*)d_in[2];
    const float* asrc0 = (const float*)d_in[3];
    const float* adst0 = (const float*)d_in[4];
    const float* W1    = (const float*)d_in[5];
    const float* asrc1 = (const float*)d_in[6];
    const float* adst1 = (const float*)d_in[7];
    const float* W2    = (const float*)d_in[8];
    const float* asrc2 = (const float*)d_in[9];
    const float* adst2 = (const float*)d_in[10];

    int H    = in_sizes[3];            // 64
    int C    = in_sizes[9];            // 40
    int Fin  = in_sizes[2] / H;        // 256
    int N    = in_sizes[0] / Fin;      // 100000
    int E    = in_sizes[1] / 2;        // 1600000
    int Etot = E + N;
    int SB   = (N + SCAN_CHUNK - 1) / SCAN_CHUNK;

    detect_kernel<<<1, 32>>>((const unsigned int*)ei);
    zero_cnt_kernel<<<(N + 255) / 256, 256>>>(N);
    hist_kernel<<<(Etot + 255) / 256, 256>>>(ei, E, Etot, N);
    scan_reduce_kernel<<<SB, 256>>>(N);
    scan_partials_kernel<<<1, 1024>>>(SB, N);
    scan_final_kernel<<<SB, 256>>>(N);
    scatter_kernel<<<(Etot + 255) / 256, 256>>>(ei, E, Etot, N);

    int gemm_blocks = (N + 63) / 64;
    int wg_blocks   = (N + 7) / 8;

    gemm_kernel<<<gemm_blocks, 256>>>(x, 0, W0, asrc0, adst0, N, Fin, H, 0);
    agg_kernel<<<wg_blocks, 256>>>(nullptr, 1, N, H);

    gemm_kernel<<<gemm_blocks, 256>>>(nullptr, 1, W1, asrc1, adst1, N, H, H, 1);
    agg_kernel<<<wg_blocks, 256>>>(nullptr, 2, N, H);

    gemm_kernel<<<gemm_blocks, 256>>>(nullptr, 2, W2, asrc2, adst2, N, H, C, 1);
    agg_kernel<<<wg_blocks, 256>>>((float*)d_out, 0, N, C);
}

// round 5
// speedup vs baseline: 1.2147x; 1.2147x over previous
#include <cuda_runtime.h>
#include <math.h>

#define NMAX 100000
#define EMAX 1700000
#define DMAX 64
#define SCAN_CHUNK 512

// ---------------- scratch (device globals; no allocation allowed) ----------
__device__ int   g_is64;
__device__ int   g_cnt[NMAX];
__device__ int   g_off[NMAX + 1];
__device__ int   g_part[1024];
__device__ int   g_esrc[EMAX];
__device__ float g_e[EMAX];
__device__ __align__(16) float g_h[(size_t)NMAX * DMAX];
__device__ __align__(16) float g_bufA[(size_t)NMAX * DMAX];
__device__ __align__(16) float g_bufB[(size_t)NMAX * DMAX];
__device__ float g_as[NMAX];
__device__ float g_ad[NMAX];

// ---------------- dtype detection ----------------
__global__ void detect_kernel(const unsigned int* __restrict__ w) {
    if (threadIdx.x != 0 || blockIdx.x != 0) return;
    int ok64 = 1;
#pragma unroll
    for (int i = 1; i < 128; i += 2) ok64 &= (w[i] == 0u);
    g_is64 = ok64;
}

__device__ __forceinline__ int load_idx(const void* eiv, long long pos) {
    if (g_is64) return (int)((const long long*)eiv)[pos];
    return ((const int*)eiv)[pos];
}

__device__ __forceinline__ int clampN(int v, int N) {
    return (v < 0) ? 0 : (v >= N ? N - 1 : v);
}

// ---------------- CSR build ----------------
__global__ void zero_cnt_kernel(int N) {
    int i = blockIdx.x * blockDim.x + threadIdx.x;
    if (i < N) g_cnt[i] = 0;
}

__global__ void hist_kernel(const void* __restrict__ eiv, int E, int Etot, int N) {
    int i = blockIdx.x * blockDim.x + threadIdx.x;
    if (i >= Etot) return;
    int d = (i < E) ? clampN(load_idx(eiv, (long long)E + i), N) : (i - E);
    atomicAdd(&g_cnt[d], 1);
}

__global__ void scan_reduce_kernel(int N) {
    __shared__ int sh[256];
    int b = blockIdx.x, t = threadIdx.x;
    int i0 = b * SCAN_CHUNK + t * 2;
    int s = 0;
    if (i0     < N) s += g_cnt[i0];
    if (i0 + 1 < N) s += g_cnt[i0 + 1];
    sh[t] = s;
    __syncthreads();
#pragma unroll
    for (int o = 128; o; o >>= 1) {
        if (t < o) sh[t] += sh[t + o];
        __syncthreads();
    }
    if (t == 0) g_part[b] = sh[0];
}

__global__ void scan_partials_kernel(int B, int N) {
    __shared__ int sh[1024];
    int t = threadIdx.x;
    int v = (t < B) ? g_part[t] : 0;
    sh[t] = v;
    __syncthreads();
#pragma unroll
    for (int o = 1; o < 1024; o <<= 1) {
        int u = (t >= o) ? sh[t - o] : 0;
        __syncthreads();
        sh[t] += u;
        __syncthreads();
    }
    if (t < B) g_part[t] = sh[t] - v;
    if (t == 1023) g_off[N] = sh[1023];
}

__global__ void scan_final_kernel(int N) {
    __shared__ int sh[256];
    int b = blockIdx.x, t = threadIdx.x;
    int i0 = b * SCAN_CHUNK + t * 2;
    int c0 = (i0     < N) ? g_cnt[i0]     : 0;
    int c1 = (i0 + 1 < N) ? g_cnt[i0 + 1] : 0;
    int s = c0 + c1;
    sh[t] = s;
    __syncthreads();
#pragma unroll
    for (int o = 1; o < 256; o <<= 1) {
        int u = (t >= o) ? sh[t - o] : 0;
        __syncthreads();
        sh[t] += u;
        __syncthreads();
    }
    int base = g_part[b] + sh[t] - s;
    if (i0 < N)     { g_off[i0]     = base;      g_cnt[i0]     = base; }
    if (i0 + 1 < N) { g_off[i0 + 1] = base + c0; g_cnt[i0 + 1] = base + c0; }
}

__global__ void scatter_kernel(const void* __restrict__ eiv, int E, int Etot, int N) {
    int i = blockIdx.x * blockDim.x + threadIdx.x;
    if (i >= Etot) return;
    int s, d;
    if (i < E) {
        s = clampN(load_idx(eiv, i), N);
        d = clampN(load_idx(eiv, (long long)E + i), N);
    } else {
        s = d = i - E;
    }
    int p = atomicAdd(&g_cnt[d], 1);
    if (p >= 0 && p < EMAX) g_esrc[p] = s;
}

// ---------------- GEMM (128x64 tile) + fused attention dots ----------------
// h = X @ W  (X: [N,F], W: [F,D], D<=64, F%16==0); also g_as/g_ad = h @ a_s/a_d
__global__ __launch_bounds__(256) void gemm_kernel(
    const float* __restrict__ Xext, int sel_in,
    const float* __restrict__ W,
    const float* __restrict__ a_s, const float* __restrict__ a_d,
    int N, int F, int D, int relu_in)
{
    const float* X = (sel_in == 0) ? Xext
                   : (sel_in == 1 ? (const float*)g_bufA : (const float*)g_bufB);
    __shared__ __align__(16) float xs[16][132];   // [k][node 0..127], pad 4
    __shared__ __align__(16) float ws[16][64];    // [k][col]
    __shared__ float as_s[64], ad_s[64];
    int tid  = threadIdx.x;
    int row0 = blockIdx.x * 128;
    int tr = tid >> 4, tc = tid & 15;              // tr: 8-row group, tc: 4-col group
    float acc[8][4] = {};
    // load mapping: each thread loads 2 float4 of X per k-tile
    int f0 = tid * 2;                              // float4 index 0..511
    int lrow0 = f0 >> 2, lq0 = f0 & 3;
    int lrow1 = (f0 + 1) >> 2, lq1 = (f0 + 1) & 3;
    int wcol = tid & 63, wk0 = (tid >> 6) << 2;

    if (tid < 64) {
        as_s[tid] = (tid < D) ? a_s[tid] : 0.f;
        ad_s[tid] = (tid < D) ? a_d[tid] : 0.f;
    }

    for (int k0 = 0; k0 < F; k0 += 16) {
        float4 xv0 = make_float4(0.f,0.f,0.f,0.f), xv1 = make_float4(0.f,0.f,0.f,0.f);
        int gn0 = row0 + lrow0, gn1 = row0 + lrow1;
        if (gn0 < N) xv0 = reinterpret_cast<const float4*>(X + (size_t)gn0 * F + k0)[lq0];
        if (gn1 < N) xv1 = reinterpret_cast<const float4*>(X + (size_t)gn1 * F + k0)[lq1];
        if (relu_in) {
            xv0.x = fmaxf(xv0.x, 0.f); xv0.y = fmaxf(xv0.y, 0.f);
            xv0.z = fmaxf(xv0.z, 0.f); xv0.w = fmaxf(xv0.w, 0.f);
            xv1.x = fmaxf(xv1.x, 0.f); xv1.y = fmaxf(xv1.y, 0.f);
            xv1.z = fmaxf(xv1.z, 0.f); xv1.w = fmaxf(xv1.w, 0.f);
        }
        xs[lq0 * 4 + 0][lrow0] = xv0.x;
        xs[lq0 * 4 + 1][lrow0] = xv0.y;
        xs[lq0 * 4 + 2][lrow0] = xv0.z;
        xs[lq0 * 4 + 3][lrow0] = xv0.w;
        xs[lq1 * 4 + 0][lrow1] = xv1.x;
        xs[lq1 * 4 + 1][lrow1] = xv1.y;
        xs[lq1 * 4 + 2][lrow1] = xv1.z;
        xs[lq1 * 4 + 3][lrow1] = xv1.w;
#pragma unroll
        for (int j = 0; j < 4; j++) {
            int k = wk0 + j;
            ws[k][wcol] = (wcol < D) ? W[(size_t)(k0 + k) * D + wcol] : 0.f;
        }
        __syncthreads();
#pragma unroll
        for (int k = 0; k < 16; k++) {
            float4 a04 = *(const float4*)&xs[k][tr * 8];
            float4 a48 = *(const float4*)&xs[k][tr * 8 + 4];
            float4 b   = *(const float4*)&ws[k][tc * 4];
            acc[0][0] += a04.x * b.x; acc[0][1] += a04.x * b.y; acc[0][2] += a04.x * b.z; acc[0][3] += a04.x * b.w;
            acc[1][0] += a04.y * b.x; acc[1][1] += a04.y * b.y; acc[1][2] += a04.y * b.z; acc[1][3] += a04.y * b.w;
            acc[2][0] += a04.z * b.x; acc[2][1] += a04.z * b.y; acc[2][2] += a04.z * b.z; acc[2][3] += a04.z * b.w;
            acc[3][0] += a04.w * b.x; acc[3][1] += a04.w * b.y; acc[3][2] += a04.w * b.z; acc[3][3] += a04.w * b.w;
            acc[4][0] += a48.x * b.x; acc[4][1] += a48.x * b.y; acc[4][2] += a48.x * b.z; acc[4][3] += a48.x * b.w;
            acc[5][0] += a48.y * b.x; acc[5][1] += a48.y * b.y; acc[5][2] += a48.y * b.z; acc[5][3] += a48.y * b.w;
            acc[6][0] += a48.z * b.x; acc[6][1] += a48.z * b.y; acc[6][2] += a48.z * b.z; acc[6][3] += a48.z * b.w;
            acc[7][0] += a48.w * b.x; acc[7][1] += a48.w * b.y; acc[7][2] += a48.w * b.z; acc[7][3] += a48.w * b.w;
        }
        __syncthreads();
    }

    // epilogue: store h + fused attention dot-products
    float sdot[8] = {}, ddot[8] = {};
    int c0 = tc * 4;
#pragma unroll
    for (int i = 0; i < 8; i++) {
        int n = row0 + tr * 8 + i;
        bool ok = (n < N);
#pragma unroll
        for (int j = 0; j < 4; j++) {
            int c = c0 + j;
            if (ok && c < D) g_h[(size_t)n * D + c] = acc[i][j];
            float w = (c < D) ? acc[i][j] : 0.f;
            sdot[i] += w * as_s[c];
            ddot[i] += w * ad_s[c];
        }
    }
#pragma unroll
    for (int o = 8; o; o >>= 1) {
#pragma unroll
        for (int i = 0; i < 8; i++) {
            sdot[i] += __shfl_xor_sync(0xffffffffu, sdot[i], o);
            ddot[i] += __shfl_xor_sync(0xffffffffu, ddot[i], o);
        }
    }
    if (tc == 0) {
#pragma unroll
        for (int i = 0; i < 8; i++) {
            int n = row0 + tr * 8 + i;
            if (n < N) { g_as[n] = sdot[i]; g_ad[n] = ddot[i]; }
        }
    }
}

// ---------------- fused segment softmax + aggregation (warp per dst) -------
__global__ void agg_kernel(float* OUText, int sel_out, int N, int D)
{
    float* OUT = (sel_out == 0) ? OUText : (sel_out == 1 ? g_bufA : g_bufB);
    int warp = (blockIdx.x * blockDim.x + threadIdx.x) >> 5;
    int lane = threadIdx.x & 31;
    int nw = (gridDim.x * blockDim.x) >> 5;
    const float2* H2 = reinterpret_cast<const float2*>(g_h);
    int rowst = D >> 1;

    for (int n = warp; n < N; n += nw) {
        int beg = g_off[n], end = g_off[n + 1];
        float adn = g_ad[n];

        // pass 1: compute logits, cache them, segment max
        float m = -INFINITY;
        for (int p = beg + lane; p < end; p += 32) {
            float v = g_as[g_esrc[p]] + adn;
            v = (v > 0.f) ? v : 0.2f * v;
            g_e[p] = v;
            m = fmaxf(m, v);
        }
#pragma unroll
        for (int o = 16; o; o >>= 1) m = fmaxf(m, __shfl_xor_sync(0xffffffffu, m, o));

        // pass 2: exp from cached logits + segment sum (store ex back)
        float sum = 0.f;
        for (int p = beg + lane; p < end; p += 32) {
            float ex = __expf(g_e[p] - m);
            g_e[p] = ex;
            sum += ex;
        }
#pragma unroll
        for (int o = 16; o; o >>= 1) sum += __shfl_xor_sync(0xffffffffu, sum, o);
        float inv = 1.f / (sum + 1e-16f);

        // pass 3: out[n,:] = sum_e alpha_e * h[src_e,:]  (lane owns 2 cols)
        int c0 = lane * 2;
        bool act = (c0 < D);
        float2 acc = make_float2(0.f, 0.f);
        int p = beg;
        for (; p + 1 < end; p += 2) {
            float a0 = g_e[p] * inv;
            float a1 = g_e[p + 1] * inv;
            int s0 = g_esrc[p];
            int s1 = g_esrc[p + 1];
            if (act) {
                float2 h0 = H2[(size_t)s0 * rowst + lane];
                float2 h1 = H2[(size_t)s1 * rowst + lane];
                acc.x += a0 * h0.x + a1 * h1.x;
                acc.y += a0 * h0.y + a1 * h1.y;
            }
        }
        if (p < end) {
            float a0 = g_e[p] * inv;
            int s0 = g_esrc[p];
            if (act) {
                float2 h0 = H2[(size_t)s0 * rowst + lane];
                acc.x += a0 * h0.x;
                acc.y += a0 * h0.y;
            }
        }
        if (act) {
            OUT[(size_t)n * D + c0]     = acc.x;
            OUT[(size_t)n * D + c0 + 1] = acc.y;
        }
    }
}

// ---------------- launch ----------------
extern "C" void kernel_launch(void* const* d_in, const int* in_sizes, int n_in,
                              void* d_out, int out_size)
{
    const float* x     = (const float*)d_in[0];
    const void*  ei    = d_in[1];
    const float* W0    = (const float*)d_in[2];
    const float* asrc0 = (const float*)d_in[3];
    const float* adst0 = (const float*)d_in[4];
    const float* W1    = (const float*)d_in[5];
    const float* asrc1 = (const float*)d_in[6];
    const float* adst1 = (const float*)d_in[7];
    const float* W2    = (const float*)d_in[8];
    const float* asrc2 = (const float*)d_in[9];
    const float* adst2 = (const float*)d_in[10];

    int H    = in_sizes[3];            // 64
    int C    = in_sizes[9];            // 40
    int Fin  = in_sizes[2] / H;        // 256
    int N    = in_sizes[0] / Fin;      // 100000
    int E    = in_sizes[1] / 2;        // 1600000
    int Etot = E + N;
    int SB   = (N + SCAN_CHUNK - 1) / SCAN_CHUNK;

    // lazily-created side stream + events (created on first call, before capture)
    static cudaStream_t s2 = nullptr;
    static cudaEvent_t ev_fork = nullptr, ev_csr = nullptr;
    if (!s2) {
        cudaStreamCreateWithFlags(&s2, cudaStreamNonBlocking);
        cudaEventCreateWithFlags(&ev_fork, cudaEventDisableTiming);
        cudaEventCreateWithFlags(&ev_csr, cudaEventDisableTiming);
    }

    // fork: CSR build on s2, concurrent with gemm0 on the main stream
    cudaEventRecord(ev_fork, 0);
    cudaStreamWaitEvent(s2, ev_fork, 0);

    detect_kernel<<<1, 32, 0, s2>>>((const unsigned int*)ei);
    zero_cnt_kernel<<<(N + 255) / 256, 256, 0, s2>>>(N);
    hist_kernel<<<(Etot + 255) / 256, 256, 0, s2>>>(ei, E, Etot, N);
    scan_reduce_kernel<<<SB, 256, 0, s2>>>(N);
    scan_partials_kernel<<<1, 1024, 0, s2>>>(SB, N);
    scan_final_kernel<<<SB, 256, 0, s2>>>(N);
    scatter_kernel<<<(Etot + 255) / 256, 256, 0, s2>>>(ei, E, Etot, N);
    cudaEventRecord(ev_csr, s2);

    int gemm_blocks = (N + 127) / 128;
    int wg_blocks   = (N + 7) / 8;

    // gemm0 runs concurrently with CSR build
    gemm_kernel<<<gemm_blocks, 256>>>(x, 0, W0, asrc0, adst0, N, Fin, H, 0);

    // join: agg needs both gemm0 and the CSR
    cudaStreamWaitEvent(0, ev_csr, 0);
    agg_kernel<<<wg_blocks, 256>>>(nullptr, 1, N, H);

    gemm_kernel<<<gemm_blocks, 256>>>(nullptr, 1, W1, asrc1, adst1, N, H, H, 1);
    agg_kernel<<<wg_blocks, 256>>>(nullptr, 2, N, H);

    gemm_kernel<<<gemm_blocks, 256>>>(nullptr, 2, W2, asrc2, adst2, N, H, C, 1);
    agg_kernel<<<wg_blocks, 256>>>((float*)d_out, 0, N, C);
}